// round 3
// baseline (speedup 1.0000x reference)
#include <cuda_runtime.h>
#include <math.h>
#include <float.h>

// Problem dims (fixed by the reference)
#define BB   4
#define NQ   512
#define MK   2048
#define CD   1024
#define NH   16
#define DH   64
#define BHC  (BB*NH)     // 64 batched heads
// SCALE = 1/sqrt(64)
#define ATTN_SCALE 0.125f

// ---------------------------------------------------------------------------
// Scratch (device globals — no allocation allowed in kernel_launch)
// ---------------------------------------------------------------------------
__device__ float g_Q[(size_t)BHC * NQ * DH];   //  8 MB  [bh][n][d]
__device__ float g_K[(size_t)BHC * MK * DH];   // 32 MB  [bh][m][d]
__device__ float g_V[(size_t)BHC * MK * DH];   // 32 MB  [bh][m][d]
__device__ float g_S[(size_t)BHC * NQ * MK];   // 256 MB [bh][n][m]
__device__ float g_O[(size_t)BB * NQ * CD];    //  8 MB  [b][n][h*64+d]

// ---------------------------------------------------------------------------
// Kernel 1: C = A @ W^T + bias   (torch nn.Linear semantics)
//   A: [rows, 1024] row-major,  W: [1024 out, 1024 in] row-major
//   trans_out=1: write to [B, H, S, D] layout (S = seqlen per batch)
//   trans_out=0: write row-major [rows, 1024]
// 128x128 tile, BK=16, 256 threads, 8x8 microtile per thread.
// ---------------------------------------------------------------------------
__global__ __launch_bounds__(256) void gemm_nt_bias(
    const float* __restrict__ A, const float* __restrict__ W,
    const float* __restrict__ bias, float* __restrict__ C,
    int S, int trans_out)
{
    __shared__ float As[16][128];
    __shared__ float Ws[16][128];

    const int tid = threadIdx.x;
    const int tx = tid & 15;        // 0..15  -> 8 cols each
    const int ty = tid >> 4;        // 0..15  -> 8 rows each
    const int rowBase = blockIdx.y * 128;
    const int colBase = blockIdx.x * 128;

    const float* Ap = A + (size_t)rowBase * CD;
    const float* Wp = W + (size_t)colBase * CD;

    const int lr = tid >> 2;        // 0..63
    const int lk = (tid & 3) * 4;   // 0,4,8,12

    float acc[8][8];
#pragma unroll
    for (int i = 0; i < 8; i++)
#pragma unroll
        for (int j = 0; j < 8; j++) acc[i][j] = 0.f;

    for (int kt = 0; kt < CD; kt += 16) {
#pragma unroll
        for (int h = 0; h < 2; h++) {
            const int r = lr + h * 64;
            float4 a = *(const float4*)(Ap + (size_t)r * CD + kt + lk);
            As[lk + 0][r] = a.x; As[lk + 1][r] = a.y;
            As[lk + 2][r] = a.z; As[lk + 3][r] = a.w;
            float4 w = *(const float4*)(Wp + (size_t)r * CD + kt + lk);
            Ws[lk + 0][r] = w.x; Ws[lk + 1][r] = w.y;
            Ws[lk + 2][r] = w.z; Ws[lk + 3][r] = w.w;
        }
        __syncthreads();
#pragma unroll
        for (int kk = 0; kk < 16; kk++) {
            float af[8], bf[8];
            *(float4*)(af)     = *(const float4*)(&As[kk][ty * 8]);
            *(float4*)(af + 4) = *(const float4*)(&As[kk][ty * 8 + 4]);
            *(float4*)(bf)     = *(const float4*)(&Ws[kk][tx * 8]);
            *(float4*)(bf + 4) = *(const float4*)(&Ws[kk][tx * 8 + 4]);
#pragma unroll
            for (int i = 0; i < 8; i++)
#pragma unroll
                for (int j = 0; j < 8; j++)
                    acc[i][j] = fmaf(af[i], bf[j], acc[i][j]);
        }
        __syncthreads();
    }

    if (trans_out) {
        // whole block lies inside one batch b (S is a multiple of 128)
        const int b  = rowBase / S;
        const int s0 = rowBase - b * S;
#pragma unroll
        for (int i = 0; i < 8; i++) {
            const int s = s0 + ty * 8 + i;
#pragma unroll
            for (int j = 0; j < 8; j++) {
                const int c = colBase + tx * 8 + j;
                const int hh = c >> 6, d = c & 63;
                C[(((size_t)(b * NH + hh)) * S + s) * DH + d] = acc[i][j] + bias[c];
            }
        }
    } else {
#pragma unroll
        for (int i = 0; i < 8; i++) {
            const int r = rowBase + ty * 8 + i;
#pragma unroll
            for (int j = 0; j < 8; j++) {
                const int c = colBase + tx * 8 + j;
                C[(size_t)r * CD + c] = acc[i][j] + bias[c];
            }
        }
    }
}

// ---------------------------------------------------------------------------
// Kernel 2: scores[bh][n][m] = SCALE * sum_d Q[bh][n][d] * K[bh][m][d]
// 128(n) x 128(m) tile, K-loop over D=64.
// ---------------------------------------------------------------------------
__global__ __launch_bounds__(256) void qk_kernel(
    const float* __restrict__ Q, const float* __restrict__ K,
    float* __restrict__ Sout)
{
    __shared__ float Qs[16][128];
    __shared__ float Ks[16][128];

    const int tid = threadIdx.x;
    const int tx = tid & 15;
    const int ty = tid >> 4;
    const int bh = blockIdx.z;
    const int nBase = blockIdx.y * 128;
    const int mBase = blockIdx.x * 128;

    const float* Qp = Q + (size_t)bh * NQ * DH + (size_t)nBase * DH;
    const float* Kp = K + (size_t)bh * MK * DH + (size_t)mBase * DH;

    const int lr = tid >> 2;
    const int lk = (tid & 3) * 4;

    float acc[8][8];
#pragma unroll
    for (int i = 0; i < 8; i++)
#pragma unroll
        for (int j = 0; j < 8; j++) acc[i][j] = 0.f;

    for (int kt = 0; kt < DH; kt += 16) {
#pragma unroll
        for (int h = 0; h < 2; h++) {
            const int r = lr + h * 64;
            float4 q = *(const float4*)(Qp + (size_t)r * DH + kt + lk);
            Qs[lk + 0][r] = q.x; Qs[lk + 1][r] = q.y;
            Qs[lk + 2][r] = q.z; Qs[lk + 3][r] = q.w;
            float4 k = *(const float4*)(Kp + (size_t)r * DH + kt + lk);
            Ks[lk + 0][r] = k.x; Ks[lk + 1][r] = k.y;
            Ks[lk + 2][r] = k.z; Ks[lk + 3][r] = k.w;
        }
        __syncthreads();
#pragma unroll
        for (int kk = 0; kk < 16; kk++) {
            float af[8], bf[8];
            *(float4*)(af)     = *(const float4*)(&Qs[kk][ty * 8]);
            *(float4*)(af + 4) = *(const float4*)(&Qs[kk][ty * 8 + 4]);
            *(float4*)(bf)     = *(const float4*)(&Ks[kk][tx * 8]);
            *(float4*)(bf + 4) = *(const float4*)(&Ks[kk][tx * 8 + 4]);
#pragma unroll
            for (int i = 0; i < 8; i++)
#pragma unroll
                for (int j = 0; j < 8; j++)
                    acc[i][j] = fmaf(af[i], bf[j], acc[i][j]);
        }
        __syncthreads();
    }

    float* So = Sout + (size_t)bh * NQ * MK;
#pragma unroll
    for (int i = 0; i < 8; i++) {
        const int n = nBase + ty * 8 + i;
#pragma unroll
        for (int j = 0; j < 8; j++) {
            const int m = mBase + tx * 8 + j;
            So[(size_t)n * MK + m] = acc[i][j] * ATTN_SCALE;
        }
    }
}

// ---------------------------------------------------------------------------
// Kernel 3: masked softmax over M, in place on g_S.
// One block per (bh, n) row; 256 threads x 8 elements.
// ---------------------------------------------------------------------------
__global__ __launch_bounds__(256) void softmax_kernel(
    float* __restrict__ Sm, const int* __restrict__ mask)
{
    const int n  = blockIdx.x;
    const int bh = blockIdx.y;
    const int b  = bh >> 4;

    float* row = Sm + (size_t)bh * NQ * MK + (size_t)n * MK;
    const int* mrow = mask + (size_t)b * MK;

    const int tid = threadIdx.x;
    const int m0 = tid * 8;

    float4 s0 = *(const float4*)(row + m0);
    float4 s1 = *(const float4*)(row + m0 + 4);
    int4 k0 = *(const int4*)(mrow + m0);
    int4 k1 = *(const int4*)(mrow + m0 + 4);

    float v[8];
    v[0] = k0.x ? s0.x : -FLT_MAX;
    v[1] = k0.y ? s0.y : -FLT_MAX;
    v[2] = k0.z ? s0.z : -FLT_MAX;
    v[3] = k0.w ? s0.w : -FLT_MAX;
    v[4] = k1.x ? s1.x : -FLT_MAX;
    v[5] = k1.y ? s1.y : -FLT_MAX;
    v[6] = k1.z ? s1.z : -FLT_MAX;
    v[7] = k1.w ? s1.w : -FLT_MAX;

    float mx = v[0];
#pragma unroll
    for (int i = 1; i < 8; i++) mx = fmaxf(mx, v[i]);

    const int lane = tid & 31, wid = tid >> 5;
    __shared__ float redm[8];
    __shared__ float reds[8];

#pragma unroll
    for (int o = 16; o > 0; o >>= 1)
        mx = fmaxf(mx, __shfl_xor_sync(0xffffffffu, mx, o));
    if (lane == 0) redm[wid] = mx;
    __syncthreads();
    float gmax = redm[0];
#pragma unroll
    for (int w = 1; w < 8; w++) gmax = fmaxf(gmax, redm[w]);

    float e[8];
    float sum = 0.f;
#pragma unroll
    for (int i = 0; i < 8; i++) {
        e[i] = expf(v[i] - gmax);   // masked: expf(~-inf) == 0
        sum += e[i];
    }
#pragma unroll
    for (int o = 16; o > 0; o >>= 1)
        sum += __shfl_xor_sync(0xffffffffu, sum, o);
    if (lane == 0) reds[wid] = sum;
    __syncthreads();
    float gsum = 0.f;
#pragma unroll
    for (int w = 0; w < 8; w++) gsum += reds[w];
    const float inv = 1.f / gsum;

    float4 o0, o1;
    o0.x = e[0] * inv; o0.y = e[1] * inv; o0.z = e[2] * inv; o0.w = e[3] * inv;
    o1.x = e[4] * inv; o1.y = e[5] * inv; o1.z = e[6] * inv; o1.w = e[7] * inv;
    *(float4*)(row + m0)     = o0;
    *(float4*)(row + m0 + 4) = o1;
}

// ---------------------------------------------------------------------------
// Kernel 4: O[b][n][h*64+d] = sum_m P[bh][n][m] * V[bh][m][d]
// 128(n) x 64(d) tile, BK=16 over m. 8x4 microtile per thread.
// ---------------------------------------------------------------------------
__global__ __launch_bounds__(256) void pv_kernel(
    const float* __restrict__ P, const float* __restrict__ V,
    float* __restrict__ O)
{
    __shared__ float Ps[16][128];
    __shared__ float Vs[16][64];

    const int tid = threadIdx.x;
    const int tx = tid & 15;     // 4 d-cols each
    const int ty = tid >> 4;     // 8 n-rows each
    const int bh = blockIdx.z;
    const int nBase = blockIdx.y * 128;

    const float* Pp = P + (size_t)bh * NQ * MK + (size_t)nBase * MK;
    const float* Vp = V + (size_t)bh * MK * DH;

    const int lr = tid >> 2;            // 0..63
    const int lk = (tid & 3) * 4;
    const int vkk = tid >> 4;           // 0..15
    const int vd  = (tid & 15) * 4;     // 0..60

    float acc[8][4];
#pragma unroll
    for (int i = 0; i < 8; i++)
#pragma unroll
        for (int j = 0; j < 4; j++) acc[i][j] = 0.f;

    for (int mt = 0; mt < MK; mt += 16) {
#pragma unroll
        for (int h = 0; h < 2; h++) {
            const int r = lr + h * 64;
            float4 p = *(const float4*)(Pp + (size_t)r * MK + mt + lk);
            Ps[lk + 0][r] = p.x; Ps[lk + 1][r] = p.y;
            Ps[lk + 2][r] = p.z; Ps[lk + 3][r] = p.w;
        }
        float4 vv = *(const float4*)(Vp + (size_t)(mt + vkk) * DH + vd);
        *(float4*)(&Vs[vkk][vd]) = vv;
        __syncthreads();
#pragma unroll
        for (int kk = 0; kk < 16; kk++) {
            float af[8], bf[4];
            *(float4*)(af)     = *(const float4*)(&Ps[kk][ty * 8]);
            *(float4*)(af + 4) = *(const float4*)(&Ps[kk][ty * 8 + 4]);
            *(float4*)(bf)     = *(const float4*)(&Vs[kk][tx * 4]);
#pragma unroll
            for (int i = 0; i < 8; i++)
#pragma unroll
                for (int j = 0; j < 4; j++)
                    acc[i][j] = fmaf(af[i], bf[j], acc[i][j]);
        }
        __syncthreads();
    }

    const int b = bh >> 4, hh = bh & 15;
#pragma unroll
    for (int i = 0; i < 8; i++) {
        const int n = nBase + ty * 8 + i;
        float* Orow = O + ((size_t)(b * NQ + n)) * CD + hh * DH;
#pragma unroll
        for (int j = 0; j < 4; j++)
            Orow[tx * 4 + j] = acc[i][j];
    }
}

// ---------------------------------------------------------------------------
// Launch
// ---------------------------------------------------------------------------
extern "C" void kernel_launch(void* const* d_in, const int* in_sizes, int n_in,
                              void* d_out, int out_size)
{
    const float* x    = (const float*)d_in[0];   // [4,512,1024]
    const float* ctx  = (const float*)d_in[1];   // [4,2048,1024]
    const int*   mask = (const int*)  d_in[2];   // [4,2048]
    const float* Wq = (const float*)d_in[3];
    const float* bq = (const float*)d_in[4];
    const float* Wk = (const float*)d_in[5];
    const float* bk = (const float*)d_in[6];
    const float* Wv = (const float*)d_in[7];
    const float* bv = (const float*)d_in[8];
    const float* Wo = (const float*)d_in[9];
    const float* bo = (const float*)d_in[10];
    float* out = (float*)d_out;                  // [4,512,1024]

    float *pQ, *pK, *pV, *pS, *pO;
    cudaGetSymbolAddress((void**)&pQ, g_Q);
    cudaGetSymbolAddress((void**)&pK, g_K);
    cudaGetSymbolAddress((void**)&pV, g_V);
    cudaGetSymbolAddress((void**)&pS, g_S);
    cudaGetSymbolAddress((void**)&pO, g_O);

    dim3 thr(256);
    // Projections (fused transpose to [B,H,S,D])
    gemm_nt_bias<<<dim3(8, 16), thr>>>(x,   Wq, bq, pQ, NQ, 1);
    gemm_nt_bias<<<dim3(8, 64), thr>>>(ctx, Wk, bk, pK, MK, 1);
    gemm_nt_bias<<<dim3(8, 64), thr>>>(ctx, Wv, bv, pV, MK, 1);
    // Attention
    qk_kernel<<<dim3(16, 4, 64), thr>>>(pQ, pK, pS);
    softmax_kernel<<<dim3(512, 64), thr>>>(pS, mask);
    pv_kernel<<<dim3(1, 4, 64), thr>>>(pS, pV, pO);
    // Output projection -> d_out
    gemm_nt_bias<<<dim3(8, 16), thr>>>(pO, Wo, bo, out, 1, 0);
}

// round 6
// speedup vs baseline: 2.5684x; 2.5684x over previous
#include <cuda_runtime.h>
#include <cuda_bf16.h>
#include <math.h>
#include <float.h>
#include <stdint.h>

// Problem dims (fixed by the reference)
#define BB   4
#define NQ   512
#define MK   2048
#define CD   1024
#define NH   16
#define DH   64
#define BHC  (BB*NH)
#define ATTN_SCALE 0.125f

// ---------------------------------------------------------------------------
// Scratch (device globals — no allocation allowed in kernel_launch)
// ---------------------------------------------------------------------------
__device__ float g_Q[(size_t)BHC * NQ * DH];   //  8 MB  [bh][n][d]
__device__ float g_K[(size_t)BHC * MK * DH];   // 32 MB  [bh][m][d]
__device__ float g_V[(size_t)BHC * MK * DH];   // 32 MB  [bh][m][d]
__device__ float g_S[(size_t)BHC * NQ * MK];   // 256 MB [bh][n][m]
__device__ float g_O[(size_t)BB * NQ * CD];    //  8 MB  [b][n][h*64+d]

// ---------------------------------------------------------------------------
// Helpers: smem addr, ldmatrix, mma.sync bf16, bf16 hi/lo split
// ---------------------------------------------------------------------------
__device__ __forceinline__ uint32_t smem_u32(const void* p) {
    uint32_t r;
    asm("{ .reg .u64 t; cvta.to.shared.u64 t, %1; cvt.u32.u64 %0, t; }"
        : "=r"(r) : "l"(p));
    return r;
}
__device__ __forceinline__ void ldsm4(uint32_t* r, uint32_t a) {
    asm volatile("ldmatrix.sync.aligned.m8n8.x4.shared.b16 {%0,%1,%2,%3}, [%4];"
                 : "=r"(r[0]), "=r"(r[1]), "=r"(r[2]), "=r"(r[3]) : "r"(a));
}
__device__ __forceinline__ void ldsm2(uint32_t* r, uint32_t a) {
    asm volatile("ldmatrix.sync.aligned.m8n8.x2.shared.b16 {%0,%1}, [%2];"
                 : "=r"(r[0]), "=r"(r[1]) : "r"(a));
}
__device__ __forceinline__ void ldsm2t(uint32_t* r, uint32_t a) {
    asm volatile("ldmatrix.sync.aligned.m8n8.x2.trans.shared.b16 {%0,%1}, [%2];"
                 : "=r"(r[0]), "=r"(r[1]) : "r"(a));
}
__device__ __forceinline__ void mma_bf(float* c, const uint32_t* a, const uint32_t* b) {
    asm volatile(
        "mma.sync.aligned.m16n8k16.row.col.f32.bf16.bf16.f32 "
        "{%0,%1,%2,%3}, {%4,%5,%6,%7}, {%8,%9}, {%0,%1,%2,%3};"
        : "+f"(c[0]), "+f"(c[1]), "+f"(c[2]), "+f"(c[3])
        : "r"(a[0]), "r"(a[1]), "r"(a[2]), "r"(a[3]), "r"(b[0]), "r"(b[1]));
}
// split 4 floats into packed bf16 hi pair + lo pair
__device__ __forceinline__ void split4(float4 v, uint2& h, uint2& l) {
    __nv_bfloat162 h0 = __floats2bfloat162_rn(v.x, v.y);
    __nv_bfloat162 h1 = __floats2bfloat162_rn(v.z, v.w);
    float rx = v.x - __low2float(h0);
    float ry = v.y - __high2float(h0);
    float rz = v.z - __low2float(h1);
    float rw = v.w - __high2float(h1);
    __nv_bfloat162 l0 = __floats2bfloat162_rn(rx, ry);
    __nv_bfloat162 l1 = __floats2bfloat162_rn(rz, rw);
    h.x = *reinterpret_cast<uint32_t*>(&h0);
    h.y = *reinterpret_cast<uint32_t*>(&h1);
    l.x = *reinterpret_cast<uint32_t*>(&l0);
    l.y = *reinterpret_cast<uint32_t*>(&l1);
}
#define SWZ(o) ((o) ^ (((o) >> 3) & 0x70))

// ---------------------------------------------------------------------------
// Kernel 1: C = A @ W^T + bias (nn.Linear). 128x128 tile, BK=32, 256 thr.
// smem stage (32 KB): A rows [128][hi 64B | lo 64B], W rows at +16KB. 2 stages.
// trans_out=1 -> write [B,H,S,D]; else row-major [rows,1024].
// ---------------------------------------------------------------------------
__global__ __launch_bounds__(256) void proj_gemm(
    const float* __restrict__ A, const float* __restrict__ W,
    const float* __restrict__ bias, float* __restrict__ C,
    int S, int trans_out)
{
    extern __shared__ char sm[];
    const int tid = threadIdx.x, lane = tid & 31, wid = tid >> 5;
    const int wm = wid >> 2, wn = wid & 3;         // warp grid 2x4
    const int g = lane >> 2, t4 = lane & 3;
    const int rowBase = blockIdx.y * 128, colBase = blockIdx.x * 128;
    const float* Ap = A + (size_t)rowBase * CD;
    const float* Wp = W + (size_t)colBase * CD;
    const uint32_t sb = smem_u32(sm);

    float acc[4][4][4];
#pragma unroll
    for (int i = 0; i < 4; i++)
#pragma unroll
        for (int j = 0; j < 4; j++)
#pragma unroll
            for (int k = 0; k < 4; k++) acc[i][j][k] = 0.f;

    const int tA = lane >> 3, rA = lane & 7;
    const uint32_t aRow = (uint32_t)(rA + 8 * (tA & 1));
    const uint32_t aCol = (uint32_t)((tA >> 1) * 16);
    const int rB = lane & 7, tB = (lane >> 3) & 1;

    for (int c = 0; c < 32; c++) {
        const int kt = c * 32;
        char* st = sm + (c & 1) * 32768;
#pragma unroll
        for (int i = 0; i < 4; i++) {
            const int idx = tid + i * 256;
            const int row = idx >> 3, c4 = idx & 7;
            float4 av = *(const float4*)(Ap + (size_t)row * CD + kt + c4 * 4);
            uint2 h, l; split4(av, h, l);
            *(uint2*)(st + SWZ((uint32_t)(row * 128 + c4 * 8))) = h;
            *(uint2*)(st + SWZ((uint32_t)(row * 128 + 64 + c4 * 8))) = l;
            float4 wv = *(const float4*)(Wp + (size_t)row * CD + kt + c4 * 4);
            split4(wv, h, l);
            *(uint2*)(st + 16384 + SWZ((uint32_t)(row * 128 + c4 * 8))) = h;
            *(uint2*)(st + 16384 + SWZ((uint32_t)(row * 128 + 64 + c4 * 8))) = l;
        }
        __syncthreads();
        const uint32_t sA = sb + (c & 1) * 32768;
        const uint32_t sB = sA + 16384;
#pragma unroll
        for (int s = 0; s < 2; s++) {
            uint32_t ah[4][4], al[4][4];
#pragma unroll
            for (int mt = 0; mt < 4; mt++) {
                const uint32_t off = (uint32_t)((wm * 64 + mt * 16 + aRow) * 128)
                                   + (uint32_t)(s * 32) + aCol;
                ldsm4(ah[mt], sA + SWZ(off));
                ldsm4(al[mt], sA + SWZ(off + 64));
            }
#pragma unroll
            for (int nt = 0; nt < 4; nt++) {
                const uint32_t boff = (uint32_t)((wn * 32 + nt * 8 + rB) * 128)
                                    + (uint32_t)(s * 32 + tB * 16);
                uint32_t bh[2], bl[2];
                ldsm2(bh, sB + SWZ(boff));
                ldsm2(bl, sB + SWZ(boff + 64));
#pragma unroll
                for (int mt = 0; mt < 4; mt++) {
                    mma_bf(acc[mt][nt], ah[mt], bh);
                    mma_bf(acc[mt][nt], al[mt], bh);
                    mma_bf(acc[mt][nt], ah[mt], bl);
                }
            }
        }
    }

#pragma unroll
    for (int mt = 0; mt < 4; mt++) {
        const int r0 = rowBase + wm * 64 + mt * 16 + g;
#pragma unroll
        for (int nt = 0; nt < 4; nt++) {
            const int col = colBase + wn * 32 + nt * 8 + 2 * t4;
            const float bx = bias[col], by = bias[col + 1];
            float2 v0 = make_float2(acc[mt][nt][0] + bx, acc[mt][nt][1] + by);
            float2 v1 = make_float2(acc[mt][nt][2] + bx, acc[mt][nt][3] + by);
            if (trans_out) {
                const int b2 = rowBase / S;
                const int srow = r0 - b2 * S;
                const int hh = col >> 6, d = col & 63;
                float* p0 = C + (((size_t)(b2 * NH + hh)) * S + srow) * DH + d;
                *(float2*)p0 = v0;
                *(float2*)(p0 + 8 * DH) = v1;
            } else {
                float* p0 = C + (size_t)r0 * CD + col;
                *(float2*)p0 = v0;
                *(float2*)(p0 + 8 * CD) = v1;
            }
        }
    }
}

// ---------------------------------------------------------------------------
// Kernel 2: S[bh][n][m] = SCALE * sum_d Q[n][d] K[m][d]. 128x128 tile, k=64.
// smem: Qhi 0 | Qlo 16K | Khi 32K | Klo 48K  (single stage)
// ---------------------------------------------------------------------------
__global__ __launch_bounds__(256) void qk_tc(
    const float* __restrict__ Q, const float* __restrict__ K,
    float* __restrict__ Sout)
{
    extern __shared__ char sm[];
    const int tid = threadIdx.x, lane = tid & 31, wid = tid >> 5;
    const int wm = wid >> 2, wn = wid & 3;
    const int g = lane >> 2, t4 = lane & 3;
    const int bh = blockIdx.z;
    const int nBase = blockIdx.y * 128, mBase = blockIdx.x * 128;
    const float* Qp = Q + (size_t)bh * NQ * DH + (size_t)nBase * DH;
    const float* Kp = K + (size_t)bh * MK * DH + (size_t)mBase * DH;
    const uint32_t sb = smem_u32(sm);

#pragma unroll
    for (int i = 0; i < 8; i++) {
        const int idx = tid + i * 256;
        const int row = idx >> 4, c4 = idx & 15;
        const uint32_t off = SWZ((uint32_t)(row * 128 + c4 * 8));
        float4 qv = *(const float4*)(Qp + (size_t)row * DH + c4 * 4);
        uint2 h, l; split4(qv, h, l);
        *(uint2*)(sm + off) = h;
        *(uint2*)(sm + 16384 + off) = l;
        float4 kv = *(const float4*)(Kp + (size_t)row * DH + c4 * 4);
        split4(kv, h, l);
        *(uint2*)(sm + 32768 + off) = h;
        *(uint2*)(sm + 49152 + off) = l;
    }
    __syncthreads();

    float acc[4][4][4];
#pragma unroll
    for (int i = 0; i < 4; i++)
#pragma unroll
        for (int j = 0; j < 4; j++)
#pragma unroll
            for (int k = 0; k < 4; k++) acc[i][j][k] = 0.f;

    const int tA = lane >> 3, rA = lane & 7;
    const uint32_t aRow = (uint32_t)(rA + 8 * (tA & 1));
    const uint32_t aCol = (uint32_t)((tA >> 1) * 16);
    const int rB = lane & 7, tB = (lane >> 3) & 1;

#pragma unroll
    for (int s = 0; s < 4; s++) {
        uint32_t ah[4][4], al[4][4];
#pragma unroll
        for (int mt = 0; mt < 4; mt++) {
            const uint32_t off = (uint32_t)((wm * 64 + mt * 16 + aRow) * 128)
                               + (uint32_t)(s * 32) + aCol;
            ldsm4(ah[mt], sb + SWZ(off));
            ldsm4(al[mt], sb + 16384 + SWZ(off));
        }
#pragma unroll
        for (int nt = 0; nt < 4; nt++) {
            const uint32_t boff = (uint32_t)((wn * 32 + nt * 8 + rB) * 128)
                                + (uint32_t)(s * 32 + tB * 16);
            uint32_t bh2[2], bl2[2];
            ldsm2(bh2, sb + 32768 + SWZ(boff));
            ldsm2(bl2, sb + 49152 + SWZ(boff));
#pragma unroll
            for (int mt = 0; mt < 4; mt++) {
                mma_bf(acc[mt][nt], ah[mt], bh2);
                mma_bf(acc[mt][nt], al[mt], bh2);
                mma_bf(acc[mt][nt], ah[mt], bl2);
            }
        }
    }

    float* So = Sout + (size_t)bh * NQ * MK;
#pragma unroll
    for (int mt = 0; mt < 4; mt++) {
        const int n0 = nBase + wm * 64 + mt * 16 + g;
#pragma unroll
        for (int nt = 0; nt < 4; nt++) {
            const int m = mBase + wn * 32 + nt * 8 + 2 * t4;
            float2 v0 = make_float2(acc[mt][nt][0] * ATTN_SCALE,
                                    acc[mt][nt][1] * ATTN_SCALE);
            float2 v1 = make_float2(acc[mt][nt][2] * ATTN_SCALE,
                                    acc[mt][nt][3] * ATTN_SCALE);
            *(float2*)(So + (size_t)n0 * MK + m) = v0;
            *(float2*)(So + (size_t)(n0 + 8) * MK + m) = v1;
        }
    }
}

// ---------------------------------------------------------------------------
// Kernel 3: masked softmax over M, in place on g_S (unchanged).
// ---------------------------------------------------------------------------
__global__ __launch_bounds__(256) void softmax_kernel(
    float* __restrict__ Sm, const int* __restrict__ mask)
{
    const int n  = blockIdx.x;
    const int bh = blockIdx.y;
    const int b  = bh >> 4;

    float* row = Sm + (size_t)bh * NQ * MK + (size_t)n * MK;
    const int* mrow = mask + (size_t)b * MK;

    const int tid = threadIdx.x;
    const int m0 = tid * 8;

    float4 s0 = *(const float4*)(row + m0);
    float4 s1 = *(const float4*)(row + m0 + 4);
    int4 k0 = *(const int4*)(mrow + m0);
    int4 k1 = *(const int4*)(mrow + m0 + 4);

    float v[8];
    v[0] = k0.x ? s0.x : -FLT_MAX;
    v[1] = k0.y ? s0.y : -FLT_MAX;
    v[2] = k0.z ? s0.z : -FLT_MAX;
    v[3] = k0.w ? s0.w : -FLT_MAX;
    v[4] = k1.x ? s1.x : -FLT_MAX;
    v[5] = k1.y ? s1.y : -FLT_MAX;
    v[6] = k1.z ? s1.z : -FLT_MAX;
    v[7] = k1.w ? s1.w : -FLT_MAX;

    float mx = v[0];
#pragma unroll
    for (int i = 1; i < 8; i++) mx = fmaxf(mx, v[i]);

    const int lane = tid & 31, wwid = tid >> 5;
    __shared__ float redm[8];
    __shared__ float reds[8];

#pragma unroll
    for (int o = 16; o > 0; o >>= 1)
        mx = fmaxf(mx, __shfl_xor_sync(0xffffffffu, mx, o));
    if (lane == 0) redm[wwid] = mx;
    __syncthreads();
    float gmax = redm[0];
#pragma unroll
    for (int w = 1; w < 8; w++) gmax = fmaxf(gmax, redm[w]);

    float e[8];
    float sum = 0.f;
#pragma unroll
    for (int i = 0; i < 8; i++) {
        e[i] = expf(v[i] - gmax);
        sum += e[i];
    }
#pragma unroll
    for (int o = 16; o > 0; o >>= 1)
        sum += __shfl_xor_sync(0xffffffffu, sum, o);
    if (lane == 0) reds[wwid] = sum;
    __syncthreads();
    float gsum = 0.f;
#pragma unroll
    for (int w = 0; w < 8; w++) gsum += reds[w];
    const float inv = 1.f / gsum;

    float4 o0, o1;
    o0.x = e[0] * inv; o0.y = e[1] * inv; o0.z = e[2] * inv; o0.w = e[3] * inv;
    o1.x = e[4] * inv; o1.y = e[5] * inv; o1.z = e[6] * inv; o1.w = e[7] * inv;
    *(float4*)(row + m0)     = o0;
    *(float4*)(row + m0 + 4) = o1;
}

// ---------------------------------------------------------------------------
// Kernel 4: O[b][n][h*64+d] = sum_m P[n][m] V[m][d]. 128x64 tile, BK=32.
// smem stage (24 KB): P rows [128][hi|lo], Vhi @16K (4KB), Vlo @20K. 2 stages.
// ---------------------------------------------------------------------------
__global__ __launch_bounds__(256) void pv_tc(
    const float* __restrict__ P, const float* __restrict__ V,
    float* __restrict__ O)
{
    extern __shared__ char sm[];
    const int tid = threadIdx.x, lane = tid & 31, wid = tid >> 5;
    const int wm = wid >> 1, wd = wid & 1;         // warp grid 4x2
    const int g = lane >> 2, t4 = lane & 3;
    const int bh = blockIdx.z;
    const int nBase = blockIdx.y * 128;
    const float* Pp = P + (size_t)bh * NQ * MK + (size_t)nBase * MK;
    const float* Vp = V + (size_t)bh * MK * DH;
    const uint32_t sb = smem_u32(sm);

    float acc[2][4][4];
#pragma unroll
    for (int i = 0; i < 2; i++)
#pragma unroll
        for (int j = 0; j < 4; j++)
#pragma unroll
            for (int k = 0; k < 4; k++) acc[i][j][k] = 0.f;

    const int tA = lane >> 3, rA = lane & 7;
    const uint32_t aRow = (uint32_t)(rA + 8 * (tA & 1));
    const uint32_t aCol = (uint32_t)((tA >> 1) * 16);
    const int rB = lane & 7, tB = (lane >> 3) & 1;

    for (int c = 0; c < 64; c++) {
        const int kt = c * 32;
        char* st = sm + (c & 1) * 24576;
#pragma unroll
        for (int i = 0; i < 4; i++) {
            const int idx = tid + i * 256;
            const int row = idx >> 3, c4 = idx & 7;
            float4 pv4 = *(const float4*)(Pp + (size_t)row * MK + kt + c4 * 4);
            uint2 h, l; split4(pv4, h, l);
            *(uint2*)(st + SWZ((uint32_t)(row * 128 + c4 * 8))) = h;
            *(uint2*)(st + SWZ((uint32_t)(row * 128 + 64 + c4 * 8))) = l;
        }
#pragma unroll
        for (int i = 0; i < 2; i++) {
            const int idx = tid + i * 256;
            const int row = idx >> 4, c4 = idx & 15;
            float4 vv = *(const float4*)(Vp + (size_t)(kt + row) * DH + c4 * 4);
            uint2 h, l; split4(vv, h, l);
            const uint32_t off = SWZ((uint32_t)(row * 128 + c4 * 8));
            *(uint2*)(st + 16384 + off) = h;
            *(uint2*)(st + 20480 + off) = l;
        }
        __syncthreads();
        const uint32_t sP  = sb + (c & 1) * 24576;
        const uint32_t sVh = sP + 16384;
        const uint32_t sVl = sP + 20480;
#pragma unroll
        for (int s = 0; s < 2; s++) {
            uint32_t ah[2][4], al[2][4];
#pragma unroll
            for (int mt = 0; mt < 2; mt++) {
                const uint32_t off = (uint32_t)((wm * 32 + mt * 16 + aRow) * 128)
                                   + (uint32_t)(s * 32) + aCol;
                ldsm4(ah[mt], sP + SWZ(off));
                ldsm4(al[mt], sP + SWZ(off + 64));
            }
#pragma unroll
            for (int nt = 0; nt < 4; nt++) {
                const uint32_t voff = (uint32_t)((s * 16 + tB * 8 + rB) * 128
                                                 + wd * 64 + nt * 16);
                uint32_t bh2[2], bl2[2];
                ldsm2t(bh2, sVh + SWZ(voff));
                ldsm2t(bl2, sVl + SWZ(voff));
#pragma unroll
                for (int mt = 0; mt < 2; mt++) {
                    mma_bf(acc[mt][nt], ah[mt], bh2);
                    mma_bf(acc[mt][nt], al[mt], bh2);
                    mma_bf(acc[mt][nt], ah[mt], bl2);
                }
            }
        }
    }

    const int b = bh >> 4, hh = bh & 15;
#pragma unroll
    for (int mt = 0; mt < 2; mt++) {
        const int n0 = nBase + wm * 32 + mt * 16 + g;
#pragma unroll
        for (int nt = 0; nt < 4; nt++) {
            const int d = wd * 32 + nt * 8 + 2 * t4;
            float* p0 = O + ((size_t)(b * NQ + n0)) * CD + hh * DH + d;
            *(float2*)p0 = make_float2(acc[mt][nt][0], acc[mt][nt][1]);
            *(float2*)(p0 + 8 * CD) = make_float2(acc[mt][nt][2], acc[mt][nt][3]);
        }
    }
}

// ---------------------------------------------------------------------------
// Launch
// ---------------------------------------------------------------------------
extern "C" void kernel_launch(void* const* d_in, const int* in_sizes, int n_in,
                              void* d_out, int out_size)
{
    const float* x    = (const float*)d_in[0];
    const float* ctx  = (const float*)d_in[1];
    const int*   mask = (const int*)  d_in[2];
    const float* Wq = (const float*)d_in[3];
    const float* bq = (const float*)d_in[4];
    const float* Wk = (const float*)d_in[5];
    const float* bk = (const float*)d_in[6];
    const float* Wv = (const float*)d_in[7];
    const float* bv = (const float*)d_in[8];
    const float* Wo = (const float*)d_in[9];
    const float* bo = (const float*)d_in[10];
    float* out = (float*)d_out;

    float *pQ, *pK, *pV, *pS, *pO;
    cudaGetSymbolAddress((void**)&pQ, g_Q);
    cudaGetSymbolAddress((void**)&pK, g_K);
    cudaGetSymbolAddress((void**)&pV, g_V);
    cudaGetSymbolAddress((void**)&pS, g_S);
    cudaGetSymbolAddress((void**)&pO, g_O);

    cudaFuncSetAttribute(proj_gemm, cudaFuncAttributeMaxDynamicSharedMemorySize, 65536);
    cudaFuncSetAttribute(qk_tc,     cudaFuncAttributeMaxDynamicSharedMemorySize, 65536);
    cudaFuncSetAttribute(pv_tc,     cudaFuncAttributeMaxDynamicSharedMemorySize, 49152);

    proj_gemm<<<dim3(8, 16), 256, 65536>>>(x,   Wq, bq, pQ, NQ, 1);
    proj_gemm<<<dim3(8, 64), 256, 65536>>>(ctx, Wk, bk, pK, MK, 1);
    proj_gemm<<<dim3(8, 64), 256, 65536>>>(ctx, Wv, bv, pV, MK, 1);
    qk_tc<<<dim3(16, 4, 64), 256, 65536>>>(pQ, pK, pS);
    softmax_kernel<<<dim3(512, 64), 256>>>(pS, mask);
    pv_tc<<<dim3(1, 4, 64), 256, 49152>>>(pS, pV, pO);
    proj_gemm<<<dim3(8, 16), 256, 65536>>>(pO, Wo, bo, out, 1, 0);
}

// round 9
// speedup vs baseline: 3.4500x; 1.3432x over previous
#include <cuda_runtime.h>
#include <cuda_bf16.h>
#include <math.h>
#include <float.h>
#include <stdint.h>

#define BB   4
#define NQ   512
#define MK   2048
#define CD   1024
#define NH   16
#define DH   64
#define BHC  (BB*NH)
#define ATTN_SCALE 0.125f

// ---------------------------------------------------------------------------
// Scratch (device globals)
// ---------------------------------------------------------------------------
__device__ __nv_bfloat16 g_Qh[(size_t)BHC * NQ * DH];
__device__ __nv_bfloat16 g_Ql[(size_t)BHC * NQ * DH];
__device__ __nv_bfloat16 g_Kh[(size_t)BHC * MK * DH];
__device__ __nv_bfloat16 g_Kl[(size_t)BHC * MK * DH];
__device__ __nv_bfloat16 g_Vh[(size_t)BHC * MK * DH];
__device__ __nv_bfloat16 g_Vl[(size_t)BHC * MK * DH];
__device__ float g_O[(size_t)BB * NQ * CD];

// ---------------------------------------------------------------------------
// Helpers
// ---------------------------------------------------------------------------
__device__ __forceinline__ uint32_t smem_u32(const void* p) {
    uint32_t r;
    asm("{ .reg .u64 t; cvta.to.shared.u64 t, %1; cvt.u32.u64 %0, t; }"
        : "=r"(r) : "l"(p));
    return r;
}
__device__ __forceinline__ void ldsm4(uint32_t* r, uint32_t a) {
    asm volatile("ldmatrix.sync.aligned.m8n8.x4.shared.b16 {%0,%1,%2,%3}, [%4];"
                 : "=r"(r[0]), "=r"(r[1]), "=r"(r[2]), "=r"(r[3]) : "r"(a));
}
__device__ __forceinline__ void ldsm2(uint32_t* r, uint32_t a) {
    asm volatile("ldmatrix.sync.aligned.m8n8.x2.shared.b16 {%0,%1}, [%2];"
                 : "=r"(r[0]), "=r"(r[1]) : "r"(a));
}
__device__ __forceinline__ void ldsm2t(uint32_t* r, uint32_t a) {
    asm volatile("ldmatrix.sync.aligned.m8n8.x2.trans.shared.b16 {%0,%1}, [%2];"
                 : "=r"(r[0]), "=r"(r[1]) : "r"(a));
}
__device__ __forceinline__ void mma_bf(float* c, const uint32_t* a, const uint32_t* b) {
    asm volatile(
        "mma.sync.aligned.m16n8k16.row.col.f32.bf16.bf16.f32 "
        "{%0,%1,%2,%3}, {%4,%5,%6,%7}, {%8,%9}, {%0,%1,%2,%3};"
        : "+f"(c[0]), "+f"(c[1]), "+f"(c[2]), "+f"(c[3])
        : "r"(a[0]), "r"(a[1]), "r"(a[2]), "r"(a[3]), "r"(b[0]), "r"(b[1]));
}
__device__ __forceinline__ void split4(float4 v, uint2& h, uint2& l) {
    __nv_bfloat162 h0 = __floats2bfloat162_rn(v.x, v.y);
    __nv_bfloat162 h1 = __floats2bfloat162_rn(v.z, v.w);
    float rx = v.x - __low2float(h0);
    float ry = v.y - __high2float(h0);
    float rz = v.z - __low2float(h1);
    float rw = v.w - __high2float(h1);
    __nv_bfloat162 l0 = __floats2bfloat162_rn(rx, ry);
    __nv_bfloat162 l1 = __floats2bfloat162_rn(rz, rw);
    h.x = *reinterpret_cast<uint32_t*>(&h0);
    h.y = *reinterpret_cast<uint32_t*>(&h1);
    l.x = *reinterpret_cast<uint32_t*>(&l0);
    l.y = *reinterpret_cast<uint32_t*>(&l1);
}
__device__ __forceinline__ uint32_t packbf(float a, float b) {
    __nv_bfloat162 p = __floats2bfloat162_rn(a, b);
    return *reinterpret_cast<uint32_t*>(&p);
}
__device__ __forceinline__ void cpa(uint32_t dst, const void* src) {
    asm volatile("cp.async.cg.shared.global [%0], [%1], 16;"
                 :: "r"(dst), "l"(src) : "memory");
}
#define CPA_COMMIT() asm volatile("cp.async.commit_group;" ::: "memory")
#define CPA_WAIT1()  asm volatile("cp.async.wait_group 1;" ::: "memory")
#define CPA_WAIT0()  asm volatile("cp.async.wait_group 0;" ::: "memory")
#define SWZ(o) ((o) ^ (((o) >> 3) & 0x70))

// ---------------------------------------------------------------------------
// Kernel 1: C = A @ W^T + bias (nn.Linear). 128x128 tile, BK=32, 256 thr.
// bf16_out=1 -> write bf16 hi/lo arrays in [bh][s][d] layout (Oh, Ol).
// bf16_out=0 -> write f32 row-major [rows,1024] to Cf.
// Register-prefetched global loads hidden behind MMA.
// ---------------------------------------------------------------------------
__global__ __launch_bounds__(256) void proj_gemm(
    const float* __restrict__ A, const float* __restrict__ W,
    const float* __restrict__ bias, float* __restrict__ Cf,
    __nv_bfloat16* __restrict__ Oh, __nv_bfloat16* __restrict__ Ol,
    int S, int bf16_out)
{
    extern __shared__ char sm[];
    const int tid = threadIdx.x, lane = tid & 31, wid = tid >> 5;
    const int wm = wid >> 2, wn = wid & 3;
    const int g = lane >> 2, t4 = lane & 3;
    const int rowBase = blockIdx.y * 128, colBase = blockIdx.x * 128;
    const float* Ap = A + (size_t)rowBase * CD;
    const float* Wp = W + (size_t)colBase * CD;
    const uint32_t sb = smem_u32(sm);

    float acc[4][4][4];
#pragma unroll
    for (int i = 0; i < 4; i++)
#pragma unroll
        for (int j = 0; j < 4; j++)
#pragma unroll
            for (int k = 0; k < 4; k++) acc[i][j][k] = 0.f;

    const int tA = lane >> 3, rA = lane & 7;
    const uint32_t aRow = (uint32_t)(rA + 8 * (tA & 1));
    const uint32_t aCol = (uint32_t)((tA >> 1) * 16);
    const int rB = lane & 7, tB = (lane >> 3) & 1;
    const int ldrow = tid >> 3, ldc4 = tid & 7;

    float4 ar[4], wr[4];
#pragma unroll
    for (int i = 0; i < 4; i++) {
        const int row = ldrow + i * 32;
        ar[i] = *(const float4*)(Ap + (size_t)row * CD + ldc4 * 4);
        wr[i] = *(const float4*)(Wp + (size_t)row * CD + ldc4 * 4);
    }

    for (int c = 0; c < 32; c++) {
        char* st = sm + (c & 1) * 32768;
#pragma unroll
        for (int i = 0; i < 4; i++) {
            const int row = ldrow + i * 32;
            uint2 h, l;
            split4(ar[i], h, l);
            *(uint2*)(st + SWZ((uint32_t)(row * 128 + ldc4 * 8))) = h;
            *(uint2*)(st + SWZ((uint32_t)(row * 128 + 64 + ldc4 * 8))) = l;
            split4(wr[i], h, l);
            *(uint2*)(st + 16384 + SWZ((uint32_t)(row * 128 + ldc4 * 8))) = h;
            *(uint2*)(st + 16384 + SWZ((uint32_t)(row * 128 + 64 + ldc4 * 8))) = l;
        }
        __syncthreads();

        if (c + 1 < 32) {
            const int kt = (c + 1) * 32;
#pragma unroll
            for (int i = 0; i < 4; i++) {
                const int row = ldrow + i * 32;
                ar[i] = *(const float4*)(Ap + (size_t)row * CD + kt + ldc4 * 4);
                wr[i] = *(const float4*)(Wp + (size_t)row * CD + kt + ldc4 * 4);
            }
        }

        const uint32_t sA = sb + (c & 1) * 32768;
        const uint32_t sB = sA + 16384;
#pragma unroll
        for (int s = 0; s < 2; s++) {
            uint32_t ah[4][4], al[4][4];
#pragma unroll
            for (int mt = 0; mt < 4; mt++) {
                const uint32_t off = (uint32_t)((wm * 64 + mt * 16 + aRow) * 128)
                                   + (uint32_t)(s * 32) + aCol;
                ldsm4(ah[mt], sA + SWZ(off));
                ldsm4(al[mt], sA + SWZ(off + 64));
            }
#pragma unroll
            for (int nt = 0; nt < 4; nt++) {
                const uint32_t boff = (uint32_t)((wn * 32 + nt * 8 + rB) * 128)
                                    + (uint32_t)(s * 32 + tB * 16);
                uint32_t bh2[2], bl2[2];
                ldsm2(bh2, sB + SWZ(boff));
                ldsm2(bl2, sB + SWZ(boff + 64));
#pragma unroll
                for (int mt = 0; mt < 4; mt++) {
                    mma_bf(acc[mt][nt], ah[mt], bh2);
                    mma_bf(acc[mt][nt], al[mt], bh2);
                    mma_bf(acc[mt][nt], ah[mt], bl2);
                }
            }
        }
    }

#pragma unroll
    for (int mt = 0; mt < 4; mt++) {
        const int r0 = rowBase + wm * 64 + mt * 16 + g;
#pragma unroll
        for (int nt = 0; nt < 4; nt++) {
            const int col = colBase + wn * 32 + nt * 8 + 2 * t4;
            const float bx = bias[col], by = bias[col + 1];
            float v00 = acc[mt][nt][0] + bx, v01 = acc[mt][nt][1] + by;
            float v10 = acc[mt][nt][2] + bx, v11 = acc[mt][nt][3] + by;
            if (bf16_out) {
                const int b2 = rowBase / S;
                const int srow = r0 - b2 * S;
                const int hh = col >> 6, d = col & 63;
                const size_t base = (((size_t)(b2 * NH + hh)) * S + srow) * DH + d;
                __nv_bfloat162 h0 = __floats2bfloat162_rn(v00, v01);
                *(__nv_bfloat162*)(Oh + base) = h0;
                *(__nv_bfloat162*)(Ol + base) = __floats2bfloat162_rn(
                    v00 - __low2float(h0), v01 - __high2float(h0));
                __nv_bfloat162 h1 = __floats2bfloat162_rn(v10, v11);
                *(__nv_bfloat162*)(Oh + base + 8 * DH) = h1;
                *(__nv_bfloat162*)(Ol + base + 8 * DH) = __floats2bfloat162_rn(
                    v10 - __low2float(h1), v11 - __high2float(h1));
            } else {
                float* p0 = Cf + (size_t)r0 * CD + col;
                *(float2*)p0 = make_float2(v00, v01);
                *(float2*)(p0 + 8 * CD) = make_float2(v10, v11);
            }
        }
    }
}

// ---------------------------------------------------------------------------
// Fused flash attention: per CTA = (q-tile of 128 rows, one bh).
// 256 threads; warp w owns q rows [w*16, w*16+16) x full M, online softmax.
// SMEM: [0,8K) mask bias f32; [8K,40K) Qhi|Qlo; two KV stages of 64 KB:
//   stage s at 40960+s*65536: Khi | Klo(+16K) | Vhi(+32K) | Vlo(+48K)
// ---------------------------------------------------------------------------
#define OFF_Q   8192
#define OFF_ST  40960
#define ATTN_SMEM (40960 + 2 * 65536)

__global__ __launch_bounds__(256) void attn_fused(
    const __nv_bfloat16* __restrict__ Qh, const __nv_bfloat16* __restrict__ Ql,
    const __nv_bfloat16* __restrict__ Kh, const __nv_bfloat16* __restrict__ Kl,
    const __nv_bfloat16* __restrict__ Vh, const __nv_bfloat16* __restrict__ Vl,
    const int* __restrict__ mask, float* __restrict__ O)
{
    extern __shared__ char sm[];
    const int tid = threadIdx.x, lane = tid & 31, wid = tid >> 5;
    const int g = lane >> 2, t4 = lane & 3;
    const int nb = blockIdx.x, bh = blockIdx.y;
    const int b = bh >> 4, hh = bh & 15;
    const uint32_t sb = smem_u32(sm);

    const int tA = lane >> 3, rA = lane & 7;
    const uint32_t aRow = (uint32_t)(rA + 8 * (tA & 1));
    const uint32_t aCol = (uint32_t)((tA >> 1) * 16);
    const int rB = lane & 7, tB = (lane >> 3) & 1;

    // mask -> additive bias in smem
#pragma unroll
    for (int i = 0; i < 8; i++) {
        const int idx = tid + i * 256;
        *(float*)(sm + idx * 4) = mask[(size_t)b * MK + idx] ? 0.f : -1e30f;
    }

    // async loads: group0 = Q + KV chunk0(stage0); group1 = KV chunk1(stage1)
    const int ldrow = tid >> 3, ldc4 = tid & 7;
    {
        const size_t qb = ((size_t)bh * NQ + nb * 128) * DH;
#pragma unroll
        for (int i = 0; i < 4; i++) {
            const int row = ldrow + i * 32;
            const uint32_t so = SWZ((uint32_t)(row * 128 + ldc4 * 16));
            const size_t eo = qb + (size_t)row * DH + ldc4 * 8;
            cpa(sb + OFF_Q + so, Qh + eo);
            cpa(sb + OFF_Q + 16384 + so, Ql + eo);
        }
        const size_t kb = ((size_t)bh * MK) * DH;
        const uint32_t sk = sb + OFF_ST;
#pragma unroll
        for (int i = 0; i < 4; i++) {
            const int row = ldrow + i * 32;
            const uint32_t so = SWZ((uint32_t)(row * 128 + ldc4 * 16));
            const size_t eo = kb + (size_t)row * DH + ldc4 * 8;
            cpa(sk + so, Kh + eo);
            cpa(sk + 16384 + so, Kl + eo);
            cpa(sk + 32768 + so, Vh + eo);
            cpa(sk + 49152 + so, Vl + eo);
        }
        CPA_COMMIT();
        const size_t kb1 = ((size_t)bh * MK + 128) * DH;
        const uint32_t sk1 = sb + OFF_ST + 65536;
#pragma unroll
        for (int i = 0; i < 4; i++) {
            const int row = ldrow + i * 32;
            const uint32_t so = SWZ((uint32_t)(row * 128 + ldc4 * 16));
            const size_t eo = kb1 + (size_t)row * DH + ldc4 * 8;
            cpa(sk1 + so, Kh + eo);
            cpa(sk1 + 16384 + so, Kl + eo);
            cpa(sk1 + 32768 + so, Vh + eo);
            cpa(sk1 + 49152 + so, Vl + eo);
        }
        CPA_COMMIT();
    }

    float Oa[8][4];
#pragma unroll
    for (int i = 0; i < 8; i++)
#pragma unroll
        for (int j = 0; j < 4; j++) Oa[i][j] = 0.f;
    float rm0 = -1e30f, rm1 = -1e30f, rl0 = 0.f, rl1 = 0.f;

    for (int c = 0; c < 16; c++) {
        if (c < 15) { CPA_WAIT1(); } else { CPA_WAIT0(); }
        __syncthreads();
        const uint32_t stg = sb + OFF_ST + (c & 1) * 65536;

        // S = Q K^T  (3-term bf16 split)
        float Sa[16][4];
#pragma unroll
        for (int i = 0; i < 16; i++)
#pragma unroll
            for (int j = 0; j < 4; j++) Sa[i][j] = 0.f;
#pragma unroll
        for (int s = 0; s < 4; s++) {
            uint32_t qh4[4], ql4[4];
            const uint32_t qoff = (uint32_t)((wid * 16 + aRow) * 128)
                                + (uint32_t)(s * 32) + aCol;
            ldsm4(qh4, sb + OFF_Q + SWZ(qoff));
            ldsm4(ql4, sb + OFF_Q + 16384 + SWZ(qoff));
#pragma unroll
            for (int nt = 0; nt < 16; nt++) {
                const uint32_t boff = (uint32_t)((nt * 8 + rB) * 128)
                                    + (uint32_t)(s * 32 + tB * 16);
                uint32_t kh2[2], kl2[2];
                ldsm2(kh2, stg + SWZ(boff));
                ldsm2(kl2, stg + 16384 + SWZ(boff));
                mma_bf(Sa[nt], qh4, kh2);
                mma_bf(Sa[nt], ql4, kh2);
                mma_bf(Sa[nt], qh4, kl2);
            }
        }

        // scale + mask, chunk row max
        float mx0 = -1e30f, mx1 = -1e30f;
#pragma unroll
        for (int nt = 0; nt < 16; nt++) {
            const int col = c * 128 + nt * 8 + 2 * t4;
            float2 bias2 = *(float2*)(sm + col * 4);
            Sa[nt][0] = Sa[nt][0] * ATTN_SCALE + bias2.x;
            Sa[nt][1] = Sa[nt][1] * ATTN_SCALE + bias2.y;
            Sa[nt][2] = Sa[nt][2] * ATTN_SCALE + bias2.x;
            Sa[nt][3] = Sa[nt][3] * ATTN_SCALE + bias2.y;
            mx0 = fmaxf(mx0, fmaxf(Sa[nt][0], Sa[nt][1]));
            mx1 = fmaxf(mx1, fmaxf(Sa[nt][2], Sa[nt][3]));
        }
        mx0 = fmaxf(mx0, __shfl_xor_sync(0xffffffffu, mx0, 1));
        mx0 = fmaxf(mx0, __shfl_xor_sync(0xffffffffu, mx0, 2));
        mx1 = fmaxf(mx1, __shfl_xor_sync(0xffffffffu, mx1, 1));
        mx1 = fmaxf(mx1, __shfl_xor_sync(0xffffffffu, mx1, 2));

        const float nm0 = fmaxf(rm0, mx0), nm1 = fmaxf(rm1, mx1);
        const float cor0 = __expf(rm0 - nm0), cor1 = __expf(rm1 - nm1);
        rm0 = nm0; rm1 = nm1;

        float sum0 = 0.f, sum1 = 0.f;
#pragma unroll
        for (int nt = 0; nt < 16; nt++) {
            Sa[nt][0] = __expf(Sa[nt][0] - nm0);
            Sa[nt][1] = __expf(Sa[nt][1] - nm0);
            Sa[nt][2] = __expf(Sa[nt][2] - nm1);
            Sa[nt][3] = __expf(Sa[nt][3] - nm1);
            sum0 += Sa[nt][0] + Sa[nt][1];
            sum1 += Sa[nt][2] + Sa[nt][3];
        }
        sum0 += __shfl_xor_sync(0xffffffffu, sum0, 1);
        sum0 += __shfl_xor_sync(0xffffffffu, sum0, 2);
        sum1 += __shfl_xor_sync(0xffffffffu, sum1, 1);
        sum1 += __shfl_xor_sync(0xffffffffu, sum1, 2);
        rl0 = rl0 * cor0 + sum0;
        rl1 = rl1 * cor1 + sum1;

#pragma unroll
        for (int i = 0; i < 8; i++) {
            Oa[i][0] *= cor0; Oa[i][1] *= cor0;
            Oa[i][2] *= cor1; Oa[i][3] *= cor1;
        }

        // O += P V  (P from registers, 3-term split)
#pragma unroll
        for (int kt = 0; kt < 8; kt++) {
            uint32_t ph[4], pl[4];
            {
                const float* pe = Sa[2 * kt];
                const float* po = Sa[2 * kt + 1];
                float h00 = __bfloat162float(__float2bfloat16(pe[0]));
                float h01 = __bfloat162float(__float2bfloat16(pe[1]));
                float h10 = __bfloat162float(__float2bfloat16(pe[2]));
                float h11 = __bfloat162float(__float2bfloat16(pe[3]));
                ph[0] = packbf(h00, h01);
                ph[1] = packbf(h10, h11);
                pl[0] = packbf(pe[0] - h00, pe[1] - h01);
                pl[1] = packbf(pe[2] - h10, pe[3] - h11);
                float o00 = __bfloat162float(__float2bfloat16(po[0]));
                float o01 = __bfloat162float(__float2bfloat16(po[1]));
                float o10 = __bfloat162float(__float2bfloat16(po[2]));
                float o11 = __bfloat162float(__float2bfloat16(po[3]));
                ph[2] = packbf(o00, o01);
                ph[3] = packbf(o10, o11);
                pl[2] = packbf(po[0] - o00, po[1] - o01);
                pl[3] = packbf(po[2] - o10, po[3] - o11);
            }
#pragma unroll
            for (int nt2 = 0; nt2 < 8; nt2++) {
                const uint32_t voff = (uint32_t)((kt * 16 + tB * 8 + rB) * 128
                                                 + nt2 * 16);
                uint32_t vh2[2], vl2[2];
                ldsm2t(vh2, stg + 32768 + SWZ(voff));
                ldsm2t(vl2, stg + 49152 + SWZ(voff));
                mma_bf(Oa[nt2], ph, vh2);
                mma_bf(Oa[nt2], pl, vh2);
                mma_bf(Oa[nt2], ph, vl2);
            }
        }
        __syncthreads();

        if (c < 14) {
            const size_t kb = ((size_t)bh * MK + (c + 2) * 128) * DH;
            const uint32_t sk = sb + OFF_ST + (c & 1) * 65536;
#pragma unroll
            for (int i = 0; i < 4; i++) {
                const int row = ldrow + i * 32;
                const uint32_t so = SWZ((uint32_t)(row * 128 + ldc4 * 16));
                const size_t eo = kb + (size_t)row * DH + ldc4 * 8;
                cpa(sk + so, Kh + eo);
                cpa(sk + 16384 + so, Kl + eo);
                cpa(sk + 32768 + so, Vh + eo);
                cpa(sk + 49152 + so, Vl + eo);
            }
            CPA_COMMIT();
        }
    }

    // epilogue: divide by row sums, write [b][n][hh*64+d] f32
    const float inv0 = 1.f / rl0, inv1 = 1.f / rl1;
    const int n0 = nb * 128 + wid * 16 + g;
#pragma unroll
    for (int nt2 = 0; nt2 < 8; nt2++) {
        const int d = nt2 * 8 + 2 * t4;
        float* p0 = O + ((size_t)(b * NQ + n0)) * CD + hh * DH + d;
        *(float2*)p0 = make_float2(Oa[nt2][0] * inv0, Oa[nt2][1] * inv0);
        *(float2*)(p0 + 8 * CD) = make_float2(Oa[nt2][2] * inv1, Oa[nt2][3] * inv1);
    }
}

// ---------------------------------------------------------------------------
// Launch
// ---------------------------------------------------------------------------
extern "C" void kernel_launch(void* const* d_in, const int* in_sizes, int n_in,
                              void* d_out, int out_size)
{
    const float* x    = (const float*)d_in[0];
    const float* ctx  = (const float*)d_in[1];
    const int*   mask = (const int*)  d_in[2];
    const float* Wq = (const float*)d_in[3];
    const float* bq = (const float*)d_in[4];
    const float* Wk = (const float*)d_in[5];
    const float* bk = (const float*)d_in[6];
    const float* Wv = (const float*)d_in[7];
    const float* bv = (const float*)d_in[8];
    const float* Wo = (const float*)d_in[9];
    const float* bo = (const float*)d_in[10];
    float* out = (float*)d_out;

    __nv_bfloat16 *pQh, *pQl, *pKh, *pKl, *pVh, *pVl;
    float* pO;
    cudaGetSymbolAddress((void**)&pQh, g_Qh);
    cudaGetSymbolAddress((void**)&pQl, g_Ql);
    cudaGetSymbolAddress((void**)&pKh, g_Kh);
    cudaGetSymbolAddress((void**)&pKl, g_Kl);
    cudaGetSymbolAddress((void**)&pVh, g_Vh);
    cudaGetSymbolAddress((void**)&pVl, g_Vl);
    cudaGetSymbolAddress((void**)&pO,  g_O);

    cudaFuncSetAttribute(proj_gemm, cudaFuncAttributeMaxDynamicSharedMemorySize, 65536);
    cudaFuncSetAttribute(attn_fused, cudaFuncAttributeMaxDynamicSharedMemorySize,
                         ATTN_SMEM);

    proj_gemm<<<dim3(8, 16), 256, 65536>>>(x,   Wq, bq, nullptr, pQh, pQl, NQ, 1);
    proj_gemm<<<dim3(8, 64), 256, 65536>>>(ctx, Wk, bk, nullptr, pKh, pKl, MK, 1);
    proj_gemm<<<dim3(8, 64), 256, 65536>>>(ctx, Wv, bv, nullptr, pVh, pVl, MK, 1);
    attn_fused<<<dim3(4, 64), 256, ATTN_SMEM>>>(pQh, pQl, pKh, pKl, pVh, pVl,
                                                mask, pO);
    proj_gemm<<<dim3(8, 16), 256, 65536>>>(pO, Wo, bo, out, nullptr, nullptr, 1, 0);
}

// round 10
// speedup vs baseline: 3.4616x; 1.0034x over previous
#include <cuda_runtime.h>
#include <cuda_bf16.h>
#include <math.h>
#include <float.h>
#include <stdint.h>

#define BB   4
#define NQ   512
#define MK   2048
#define CD   1024
#define NH   16
#define DH   64
#define BHC  (BB*NH)
#define ATTN_SCALE 0.125f

// ---------------------------------------------------------------------------
// Scratch (device globals)
// ---------------------------------------------------------------------------
__device__ __nv_bfloat16 g_Qh[(size_t)BHC * NQ * DH];
__device__ __nv_bfloat16 g_Ql[(size_t)BHC * NQ * DH];
__device__ __nv_bfloat16 g_Kh[(size_t)BHC * MK * DH];
__device__ __nv_bfloat16 g_Kl[(size_t)BHC * MK * DH];
__device__ __nv_bfloat16 g_Vh[(size_t)BHC * MK * DH];
__device__ __nv_bfloat16 g_Vl[(size_t)BHC * MK * DH];
__device__ float g_O[(size_t)BB * NQ * CD];

// ---------------------------------------------------------------------------
// Helpers
// ---------------------------------------------------------------------------
__device__ __forceinline__ uint32_t smem_u32(const void* p) {
    uint32_t r;
    asm("{ .reg .u64 t; cvta.to.shared.u64 t, %1; cvt.u32.u64 %0, t; }"
        : "=r"(r) : "l"(p));
    return r;
}
__device__ __forceinline__ void ldsm4(uint32_t* r, uint32_t a) {
    asm volatile("ldmatrix.sync.aligned.m8n8.x4.shared.b16 {%0,%1,%2,%3}, [%4];"
                 : "=r"(r[0]), "=r"(r[1]), "=r"(r[2]), "=r"(r[3]) : "r"(a));
}
__device__ __forceinline__ void ldsm2(uint32_t* r, uint32_t a) {
    asm volatile("ldmatrix.sync.aligned.m8n8.x2.shared.b16 {%0,%1}, [%2];"
                 : "=r"(r[0]), "=r"(r[1]) : "r"(a));
}
__device__ __forceinline__ void ldsm2t(uint32_t* r, uint32_t a) {
    asm volatile("ldmatrix.sync.aligned.m8n8.x2.trans.shared.b16 {%0,%1}, [%2];"
                 : "=r"(r[0]), "=r"(r[1]) : "r"(a));
}
__device__ __forceinline__ void mma_bf(float* c, const uint32_t* a, const uint32_t* b) {
    asm volatile(
        "mma.sync.aligned.m16n8k16.row.col.f32.bf16.bf16.f32 "
        "{%0,%1,%2,%3}, {%4,%5,%6,%7}, {%8,%9}, {%0,%1,%2,%3};"
        : "+f"(c[0]), "+f"(c[1]), "+f"(c[2]), "+f"(c[3])
        : "r"(a[0]), "r"(a[1]), "r"(a[2]), "r"(a[3]), "r"(b[0]), "r"(b[1]));
}
__device__ __forceinline__ void split4(float4 v, uint2& h, uint2& l) {
    __nv_bfloat162 h0 = __floats2bfloat162_rn(v.x, v.y);
    __nv_bfloat162 h1 = __floats2bfloat162_rn(v.z, v.w);
    float rx = v.x - __low2float(h0);
    float ry = v.y - __high2float(h0);
    float rz = v.z - __low2float(h1);
    float rw = v.w - __high2float(h1);
    __nv_bfloat162 l0 = __floats2bfloat162_rn(rx, ry);
    __nv_bfloat162 l1 = __floats2bfloat162_rn(rz, rw);
    h.x = *reinterpret_cast<uint32_t*>(&h0);
    h.y = *reinterpret_cast<uint32_t*>(&h1);
    l.x = *reinterpret_cast<uint32_t*>(&l0);
    l.y = *reinterpret_cast<uint32_t*>(&l1);
}
__device__ __forceinline__ uint32_t packbf(float a, float b) {
    __nv_bfloat162 p = __floats2bfloat162_rn(a, b);
    return *reinterpret_cast<uint32_t*>(&p);
}
__device__ __forceinline__ void cpa(uint32_t dst, const void* src) {
    asm volatile("cp.async.cg.shared.global [%0], [%1], 16;"
                 :: "r"(dst), "l"(src) : "memory");
}
#define CPA_COMMIT() asm volatile("cp.async.commit_group;" ::: "memory")
#define CPA_WAIT1()  asm volatile("cp.async.wait_group 1;" ::: "memory")
#define CPA_WAIT0()  asm volatile("cp.async.wait_group 0;" ::: "memory")
#define SWZ(o) ((o) ^ (((o) >> 3) & 0x70))

// ---------------------------------------------------------------------------
// Kernel 1: C = A @ W^T + bias (nn.Linear). 128x128 tile, BK=32, 256 thr.
// Term-major MMA issue (dependent-MMA distance 4) + double-buffered B ldsm.
// ---------------------------------------------------------------------------
__global__ __launch_bounds__(256) void proj_gemm(
    const float* __restrict__ A, const float* __restrict__ W,
    const float* __restrict__ bias, float* __restrict__ Cf,
    __nv_bfloat16* __restrict__ Oh, __nv_bfloat16* __restrict__ Ol,
    int S, int bf16_out)
{
    extern __shared__ char sm[];
    const int tid = threadIdx.x, lane = tid & 31, wid = tid >> 5;
    const int wm = wid >> 2, wn = wid & 3;
    const int g = lane >> 2, t4 = lane & 3;
    const int rowBase = blockIdx.y * 128, colBase = blockIdx.x * 128;
    const float* Ap = A + (size_t)rowBase * CD;
    const float* Wp = W + (size_t)colBase * CD;
    const uint32_t sb = smem_u32(sm);

    float acc[4][4][4];
#pragma unroll
    for (int i = 0; i < 4; i++)
#pragma unroll
        for (int j = 0; j < 4; j++)
#pragma unroll
            for (int k = 0; k < 4; k++) acc[i][j][k] = 0.f;

    const int tA = lane >> 3, rA = lane & 7;
    const uint32_t aRow = (uint32_t)(rA + 8 * (tA & 1));
    const uint32_t aCol = (uint32_t)((tA >> 1) * 16);
    const int rB = lane & 7, tB = (lane >> 3) & 1;
    const int ldrow = tid >> 3, ldc4 = tid & 7;

    float4 ar[4], wr[4];
#pragma unroll
    for (int i = 0; i < 4; i++) {
        const int row = ldrow + i * 32;
        ar[i] = *(const float4*)(Ap + (size_t)row * CD + ldc4 * 4);
        wr[i] = *(const float4*)(Wp + (size_t)row * CD + ldc4 * 4);
    }

    for (int c = 0; c < 32; c++) {
        char* st = sm + (c & 1) * 32768;
#pragma unroll
        for (int i = 0; i < 4; i++) {
            const int row = ldrow + i * 32;
            uint2 h, l;
            split4(ar[i], h, l);
            *(uint2*)(st + SWZ((uint32_t)(row * 128 + ldc4 * 8))) = h;
            *(uint2*)(st + SWZ((uint32_t)(row * 128 + 64 + ldc4 * 8))) = l;
            split4(wr[i], h, l);
            *(uint2*)(st + 16384 + SWZ((uint32_t)(row * 128 + ldc4 * 8))) = h;
            *(uint2*)(st + 16384 + SWZ((uint32_t)(row * 128 + 64 + ldc4 * 8))) = l;
        }
        __syncthreads();

        if (c + 1 < 32) {
            const int kt = (c + 1) * 32;
#pragma unroll
            for (int i = 0; i < 4; i++) {
                const int row = ldrow + i * 32;
                ar[i] = *(const float4*)(Ap + (size_t)row * CD + kt + ldc4 * 4);
                wr[i] = *(const float4*)(Wp + (size_t)row * CD + kt + ldc4 * 4);
            }
        }

        const uint32_t sA = sb + (c & 1) * 32768;
        const uint32_t sB = sA + 16384;
#pragma unroll
        for (int s = 0; s < 2; s++) {
            uint32_t ah[4][4], al[4][4];
#pragma unroll
            for (int mt = 0; mt < 4; mt++) {
                const uint32_t off = (uint32_t)((wm * 64 + mt * 16 + aRow) * 128)
                                   + (uint32_t)(s * 32) + aCol;
                ldsm4(ah[mt], sA + SWZ(off));
                ldsm4(al[mt], sA + SWZ(off + 64));
            }
            uint32_t bh2[2][2], bl2[2][2];
            {
                const uint32_t b0 = (uint32_t)((wn * 32 + rB) * 128)
                                  + (uint32_t)(s * 32 + tB * 16);
                ldsm2(bh2[0], sB + SWZ(b0));
                ldsm2(bl2[0], sB + SWZ(b0 + 64));
            }
#pragma unroll
            for (int nt = 0; nt < 4; nt++) {
                const int cur = nt & 1, nxt = cur ^ 1;
                if (nt < 3) {
                    const uint32_t bo = (uint32_t)((wn * 32 + (nt + 1) * 8 + rB) * 128)
                                      + (uint32_t)(s * 32 + tB * 16);
                    ldsm2(bh2[nxt], sB + SWZ(bo));
                    ldsm2(bl2[nxt], sB + SWZ(bo + 64));
                }
#pragma unroll
                for (int mt = 0; mt < 4; mt++) mma_bf(acc[mt][nt], ah[mt], bh2[cur]);
#pragma unroll
                for (int mt = 0; mt < 4; mt++) mma_bf(acc[mt][nt], al[mt], bh2[cur]);
#pragma unroll
                for (int mt = 0; mt < 4; mt++) mma_bf(acc[mt][nt], ah[mt], bl2[cur]);
            }
        }
    }

#pragma unroll
    for (int mt = 0; mt < 4; mt++) {
        const int r0 = rowBase + wm * 64 + mt * 16 + g;
#pragma unroll
        for (int nt = 0; nt < 4; nt++) {
            const int col = colBase + wn * 32 + nt * 8 + 2 * t4;
            const float bx = bias[col], by = bias[col + 1];
            float v00 = acc[mt][nt][0] + bx, v01 = acc[mt][nt][1] + by;
            float v10 = acc[mt][nt][2] + bx, v11 = acc[mt][nt][3] + by;
            if (bf16_out) {
                const int b2 = rowBase / S;
                const int srow = r0 - b2 * S;
                const int hh = col >> 6, d = col & 63;
                const size_t base = (((size_t)(b2 * NH + hh)) * S + srow) * DH + d;
                __nv_bfloat162 h0 = __floats2bfloat162_rn(v00, v01);
                *(__nv_bfloat162*)(Oh + base) = h0;
                *(__nv_bfloat162*)(Ol + base) = __floats2bfloat162_rn(
                    v00 - __low2float(h0), v01 - __high2float(h0));
                __nv_bfloat162 h1 = __floats2bfloat162_rn(v10, v11);
                *(__nv_bfloat162*)(Oh + base + 8 * DH) = h1;
                *(__nv_bfloat162*)(Ol + base + 8 * DH) = __floats2bfloat162_rn(
                    v10 - __low2float(h1), v11 - __high2float(h1));
            } else {
                float* p0 = Cf + (size_t)r0 * CD + col;
                *(float2*)p0 = make_float2(v00, v01);
                *(float2*)(p0 + 8 * CD) = make_float2(v10, v11);
            }
        }
    }
}

// ---------------------------------------------------------------------------
// Fused flash attention: per CTA = (q-tile of 128 rows, one bh).
// Paired n-tile MMA issue (dependent-MMA distance 2).
// ---------------------------------------------------------------------------
#define OFF_Q   8192
#define OFF_ST  40960
#define ATTN_SMEM (40960 + 2 * 65536)

__global__ __launch_bounds__(256) void attn_fused(
    const __nv_bfloat16* __restrict__ Qh, const __nv_bfloat16* __restrict__ Ql,
    const __nv_bfloat16* __restrict__ Kh, const __nv_bfloat16* __restrict__ Kl,
    const __nv_bfloat16* __restrict__ Vh, const __nv_bfloat16* __restrict__ Vl,
    const int* __restrict__ mask, float* __restrict__ O)
{
    extern __shared__ char sm[];
    const int tid = threadIdx.x, lane = tid & 31, wid = tid >> 5;
    const int g = lane >> 2, t4 = lane & 3;
    const int nb = blockIdx.x, bh = blockIdx.y;
    const int b = bh >> 4, hh = bh & 15;
    const uint32_t sb = smem_u32(sm);

    const int tA = lane >> 3, rA = lane & 7;
    const uint32_t aRow = (uint32_t)(rA + 8 * (tA & 1));
    const uint32_t aCol = (uint32_t)((tA >> 1) * 16);
    const int rB = lane & 7, tB = (lane >> 3) & 1;

#pragma unroll
    for (int i = 0; i < 8; i++) {
        const int idx = tid + i * 256;
        *(float*)(sm + idx * 4) = mask[(size_t)b * MK + idx] ? 0.f : -1e30f;
    }

    const int ldrow = tid >> 3, ldc4 = tid & 7;
    {
        const size_t qb = ((size_t)bh * NQ + nb * 128) * DH;
#pragma unroll
        for (int i = 0; i < 4; i++) {
            const int row = ldrow + i * 32;
            const uint32_t so = SWZ((uint32_t)(row * 128 + ldc4 * 16));
            const size_t eo = qb + (size_t)row * DH + ldc4 * 8;
            cpa(sb + OFF_Q + so, Qh + eo);
            cpa(sb + OFF_Q + 16384 + so, Ql + eo);
        }
        const size_t kb = ((size_t)bh * MK) * DH;
        const uint32_t sk = sb + OFF_ST;
#pragma unroll
        for (int i = 0; i < 4; i++) {
            const int row = ldrow + i * 32;
            const uint32_t so = SWZ((uint32_t)(row * 128 + ldc4 * 16));
            const size_t eo = kb + (size_t)row * DH + ldc4 * 8;
            cpa(sk + so, Kh + eo);
            cpa(sk + 16384 + so, Kl + eo);
            cpa(sk + 32768 + so, Vh + eo);
            cpa(sk + 49152 + so, Vl + eo);
        }
        CPA_COMMIT();
        const size_t kb1 = ((size_t)bh * MK + 128) * DH;
        const uint32_t sk1 = sb + OFF_ST + 65536;
#pragma unroll
        for (int i = 0; i < 4; i++) {
            const int row = ldrow + i * 32;
            const uint32_t so = SWZ((uint32_t)(row * 128 + ldc4 * 16));
            const size_t eo = kb1 + (size_t)row * DH + ldc4 * 8;
            cpa(sk1 + so, Kh + eo);
            cpa(sk1 + 16384 + so, Kl + eo);
            cpa(sk1 + 32768 + so, Vh + eo);
            cpa(sk1 + 49152 + so, Vl + eo);
        }
        CPA_COMMIT();
    }

    float Oa[8][4];
#pragma unroll
    for (int i = 0; i < 8; i++)
#pragma unroll
        for (int j = 0; j < 4; j++) Oa[i][j] = 0.f;
    float rm0 = -1e30f, rm1 = -1e30f, rl0 = 0.f, rl1 = 0.f;

    for (int c = 0; c < 16; c++) {
        if (c < 15) { CPA_WAIT1(); } else { CPA_WAIT0(); }
        __syncthreads();
        const uint32_t stg = sb + OFF_ST + (c & 1) * 65536;

        // S = Q K^T  (3-term split, paired n-tiles)
        float Sa[16][4];
#pragma unroll
        for (int i = 0; i < 16; i++)
#pragma unroll
            for (int j = 0; j < 4; j++) Sa[i][j] = 0.f;
#pragma unroll
        for (int s = 0; s < 4; s++) {
            uint32_t qh4[4], ql4[4];
            const uint32_t qoff = (uint32_t)((wid * 16 + aRow) * 128)
                                + (uint32_t)(s * 32) + aCol;
            ldsm4(qh4, sb + OFF_Q + SWZ(qoff));
            ldsm4(ql4, sb + OFF_Q + 16384 + SWZ(qoff));
#pragma unroll
            for (int np = 0; np < 8; np++) {
                const int n0 = 2 * np, n1 = 2 * np + 1;
                const uint32_t bo0 = (uint32_t)((n0 * 8 + rB) * 128)
                                   + (uint32_t)(s * 32 + tB * 16);
                const uint32_t bo1 = (uint32_t)((n1 * 8 + rB) * 128)
                                   + (uint32_t)(s * 32 + tB * 16);
                uint32_t kh0[2], kl0[2], kh1[2], kl1[2];
                ldsm2(kh0, stg + SWZ(bo0));
                ldsm2(kl0, stg + 16384 + SWZ(bo0));
                ldsm2(kh1, stg + SWZ(bo1));
                ldsm2(kl1, stg + 16384 + SWZ(bo1));
                mma_bf(Sa[n0], qh4, kh0);
                mma_bf(Sa[n1], qh4, kh1);
                mma_bf(Sa[n0], ql4, kh0);
                mma_bf(Sa[n1], ql4, kh1);
                mma_bf(Sa[n0], qh4, kl0);
                mma_bf(Sa[n1], qh4, kl1);
            }
        }

        // scale + mask, chunk row max
        float mx0 = -1e30f, mx1 = -1e30f;
#pragma unroll
        for (int nt = 0; nt < 16; nt++) {
            const int col = c * 128 + nt * 8 + 2 * t4;
            float2 bias2 = *(float2*)(sm + col * 4);
            Sa[nt][0] = Sa[nt][0] * ATTN_SCALE + bias2.x;
            Sa[nt][1] = Sa[nt][1] * ATTN_SCALE + bias2.y;
            Sa[nt][2] = Sa[nt][2] * ATTN_SCALE + bias2.x;
            Sa[nt][3] = Sa[nt][3] * ATTN_SCALE + bias2.y;
            mx0 = fmaxf(mx0, fmaxf(Sa[nt][0], Sa[nt][1]));
            mx1 = fmaxf(mx1, fmaxf(Sa[nt][2], Sa[nt][3]));
        }
        mx0 = fmaxf(mx0, __shfl_xor_sync(0xffffffffu, mx0, 1));
        mx0 = fmaxf(mx0, __shfl_xor_sync(0xffffffffu, mx0, 2));
        mx1 = fmaxf(mx1, __shfl_xor_sync(0xffffffffu, mx1, 1));
        mx1 = fmaxf(mx1, __shfl_xor_sync(0xffffffffu, mx1, 2));

        const float nm0 = fmaxf(rm0, mx0), nm1 = fmaxf(rm1, mx1);
        const float cor0 = __expf(rm0 - nm0), cor1 = __expf(rm1 - nm1);
        rm0 = nm0; rm1 = nm1;

        float sum0 = 0.f, sum1 = 0.f;
#pragma unroll
        for (int nt = 0; nt < 16; nt++) {
            Sa[nt][0] = __expf(Sa[nt][0] - nm0);
            Sa[nt][1] = __expf(Sa[nt][1] - nm0);
            Sa[nt][2] = __expf(Sa[nt][2] - nm1);
            Sa[nt][3] = __expf(Sa[nt][3] - nm1);
            sum0 += Sa[nt][0] + Sa[nt][1];
            sum1 += Sa[nt][2] + Sa[nt][3];
        }
        sum0 += __shfl_xor_sync(0xffffffffu, sum0, 1);
        sum0 += __shfl_xor_sync(0xffffffffu, sum0, 2);
        sum1 += __shfl_xor_sync(0xffffffffu, sum1, 1);
        sum1 += __shfl_xor_sync(0xffffffffu, sum1, 2);
        rl0 = rl0 * cor0 + sum0;
        rl1 = rl1 * cor1 + sum1;

#pragma unroll
        for (int i = 0; i < 8; i++) {
            Oa[i][0] *= cor0; Oa[i][1] *= cor0;
            Oa[i][2] *= cor1; Oa[i][3] *= cor1;
        }

        // O += P V  (paired n-tiles)
#pragma unroll
        for (int kt = 0; kt < 8; kt++) {
            uint32_t ph[4], pl[4];
            {
                const float* pe = Sa[2 * kt];
                const float* po = Sa[2 * kt + 1];
                float h00 = __bfloat162float(__float2bfloat16(pe[0]));
                float h01 = __bfloat162float(__float2bfloat16(pe[1]));
                float h10 = __bfloat162float(__float2bfloat16(pe[2]));
                float h11 = __bfloat162float(__float2bfloat16(pe[3]));
                ph[0] = packbf(h00, h01);
                ph[1] = packbf(h10, h11);
                pl[0] = packbf(pe[0] - h00, pe[1] - h01);
                pl[1] = packbf(pe[2] - h10, pe[3] - h11);
                float o00 = __bfloat162float(__float2bfloat16(po[0]));
                float o01 = __bfloat162float(__float2bfloat16(po[1]));
                float o10 = __bfloat162float(__float2bfloat16(po[2]));
                float o11 = __bfloat162float(__float2bfloat16(po[3]));
                ph[2] = packbf(o00, o01);
                ph[3] = packbf(o10, o11);
                pl[2] = packbf(po[0] - o00, po[1] - o01);
                pl[3] = packbf(po[2] - o10, po[3] - o11);
            }
#pragma unroll
            for (int np = 0; np < 4; np++) {
                const int n0 = 2 * np, n1 = 2 * np + 1;
                const uint32_t v0 = (uint32_t)((kt * 16 + tB * 8 + rB) * 128 + n0 * 16);
                const uint32_t v1 = (uint32_t)((kt * 16 + tB * 8 + rB) * 128 + n1 * 16);
                uint32_t vh0[2], vl0[2], vh1[2], vl1[2];
                ldsm2t(vh0, stg + 32768 + SWZ(v0));
                ldsm2t(vl0, stg + 49152 + SWZ(v0));
                ldsm2t(vh1, stg + 32768 + SWZ(v1));
                ldsm2t(vl1, stg + 49152 + SWZ(v1));
                mma_bf(Oa[n0], ph, vh0);
                mma_bf(Oa[n1], ph, vh1);
                mma_bf(Oa[n0], pl, vh0);
                mma_bf(Oa[n1], pl, vh1);
                mma_bf(Oa[n0], ph, vl0);
                mma_bf(Oa[n1], ph, vl1);
            }
        }
        __syncthreads();

        if (c < 14) {
            const size_t kb = ((size_t)bh * MK + (c + 2) * 128) * DH;
            const uint32_t sk = sb + OFF_ST + (c & 1) * 65536;
#pragma unroll
            for (int i = 0; i < 4; i++) {
                const int row = ldrow + i * 32;
                const uint32_t so = SWZ((uint32_t)(row * 128 + ldc4 * 16));
                const size_t eo = kb + (size_t)row * DH + ldc4 * 8;
                cpa(sk + so, Kh + eo);
                cpa(sk + 16384 + so, Kl + eo);
                cpa(sk + 32768 + so, Vh + eo);
                cpa(sk + 49152 + so, Vl + eo);
            }
            CPA_COMMIT();
        }
    }

    const float inv0 = 1.f / rl0, inv1 = 1.f / rl1;
    const int n0 = nb * 128 + wid * 16 + g;
#pragma unroll
    for (int nt2 = 0; nt2 < 8; nt2++) {
        const int d = nt2 * 8 + 2 * t4;
        float* p0 = O + ((size_t)(b * NQ + n0)) * CD + hh * DH + d;
        *(float2*)p0 = make_float2(Oa[nt2][0] * inv0, Oa[nt2][1] * inv0);
        *(float2*)(p0 + 8 * CD) = make_float2(Oa[nt2][2] * inv1, Oa[nt2][3] * inv1);
    }
}

// ---------------------------------------------------------------------------
// Launch
// ---------------------------------------------------------------------------
extern "C" void kernel_launch(void* const* d_in, const int* in_sizes, int n_in,
                              void* d_out, int out_size)
{
    const float* x    = (const float*)d_in[0];
    const float* ctx  = (const float*)d_in[1];
    const int*   mask = (const int*)  d_in[2];
    const float* Wq = (const float*)d_in[3];
    const float* bq = (const float*)d_in[4];
    const float* Wk = (const float*)d_in[5];
    const float* bk = (const float*)d_in[6];
    const float* Wv = (const float*)d_in[7];
    const float* bv = (const float*)d_in[8];
    const float* Wo = (const float*)d_in[9];
    const float* bo = (const float*)d_in[10];
    float* out = (float*)d_out;

    __nv_bfloat16 *pQh, *pQl, *pKh, *pKl, *pVh, *pVl;
    float* pO;
    cudaGetSymbolAddress((void**)&pQh, g_Qh);
    cudaGetSymbolAddress((void**)&pQl, g_Ql);
    cudaGetSymbolAddress((void**)&pKh, g_Kh);
    cudaGetSymbolAddress((void**)&pKl, g_Kl);
    cudaGetSymbolAddress((void**)&pVh, g_Vh);
    cudaGetSymbolAddress((void**)&pVl, g_Vl);
    cudaGetSymbolAddress((void**)&pO,  g_O);

    cudaFuncSetAttribute(proj_gemm, cudaFuncAttributeMaxDynamicSharedMemorySize, 65536);
    cudaFuncSetAttribute(attn_fused, cudaFuncAttributeMaxDynamicSharedMemorySize,
                         ATTN_SMEM);

    proj_gemm<<<dim3(8, 16), 256, 65536>>>(x,   Wq, bq, nullptr, pQh, pQl, NQ, 1);
    proj_gemm<<<dim3(8, 64), 256, 65536>>>(ctx, Wk, bk, nullptr, pKh, pKl, MK, 1);
    proj_gemm<<<dim3(8, 64), 256, 65536>>>(ctx, Wv, bv, nullptr, pVh, pVl, MK, 1);
    attn_fused<<<dim3(4, 64), 256, ATTN_SMEM>>>(pQh, pQl, pKh, pKl, pVh, pVl,
                                                mask, pO);
    proj_gemm<<<dim3(8, 16), 256, 65536>>>(pO, Wo, bo, out, nullptr, nullptr, 1, 0);
}